// round 17
// baseline (speedup 1.0000x reference)
#include <cuda_runtime.h>

// BoxBlur 13x13 reflect, (8,64,512,512) fp32. Separable, sliding-window.
// = R15 structure with ONE parameter change: TY 16 -> 8.
// Rationale: at TY=16, 3 CTAs x 65.7KB smem = 197KB carveout left only ~31KB
// of L1D, so pass-1's outgoing-row reloads (72KB live) missed to L2 (~240cyc)
// -> exposed latency capped DRAM at 70%. TY=8 halves smem (98.5KB/SM) ->
// L1D ~130KB -> reloads hit L1 (~32cyc).
// (Resubmission of R16 — container infra failed before any measurement.)

#define Wd 512
#define Hd 512
#define TY 8
#define NT 512
#define PW 513            // vs stride (conflict-free)
#define OW 513            // os stride (conflict-free)
#define KHALF 6

#define SMEM_FLOATS (TY * PW + TY * OW)
#define SMEM_BYTES  (SMEM_FLOATS * 4)       // 32,832 B -> 3 CTAs/SM (98.5KB)

__device__ __forceinline__ int reflect_i(int i, int n) {
    // jnp.pad 'reflect', pad (6) < n: single fold.
    if (i < 0) i = -i;
    if (i >= n) i = 2 * n - 2 - i;
    return i;
}

__global__ __launch_bounds__(NT, 3)
void boxblur16(const float* __restrict__ in,
               const float* __restrict__ kern,
               float* __restrict__ out) {
    extern __shared__ float sm[];
    float* __restrict__ vs = sm;             // [TY][PW]  vertical 13-sums
    float* __restrict__ os = sm + TY * PW;   // [TY][OW]  warp-private staging

    const int ytile = blockIdx.x;            // 0..63
    const int plane = blockIdx.y;
    const int y0 = ytile * TY;
    const float* __restrict__ ip = in  + (size_t)plane * (Hd * Wd);
    float*       __restrict__ op = out + (size_t)plane * (Hd * Wd);
    const int t = threadIdx.x;               // 0..511
    const float k0 = kern[0];                // 1/169

    // ---- Pass 1: vertical running 13-sum, thread t = column t ----
    if (ytile >= 1 && ytile <= 62) {
        // interior: rows y0-6 .. y0+13 all in-bounds -> pure pointer walk
        const float* __restrict__ q = ip + (y0 - KHALF) * Wd + t;
        float s = 0.0f;
        #pragma unroll
        for (int j = 0; j < 12; j++)
            s += q[j * Wd];
        #pragma unroll
        for (int j = 0; j < TY; j++) {
            s += q[(j + 12) * Wd];                  // incoming row y0+j+6
            vs[j * PW + t] = s;
            s -= q[j * Wd];                         // outgoing (L1 hit now)
        }
    } else {
        // edge tiles: reflect indexing
        float s = 0.0f;
        #pragma unroll
        for (int j = -KHALF; j < KHALF; j++)
            s += ip[reflect_i(y0 + j, Hd) * Wd + t];
        #pragma unroll
        for (int j = 0; j < TY; j++) {
            s += ip[reflect_i(y0 + j + KHALF, Hd) * Wd + t];
            vs[j * PW + t] = s;
            s -= ip[reflect_i(y0 + j - KHALF, Hd) * Wd + t];
        }
    }
    __syncthreads();   // the ONLY block-wide sync

    // ---- Pass 2 + flush: warp-private 32-column block, all 8 rows ----
    {
        const int lane = t & 31;
        const int w    = t >> 5;        // warp 0..15: columns [32w, 32w+32)
        const int rl   = lane & 7;      // row 0..7
        const int sc   = lane >> 3;     // quarter-block select 0..3
        const int xb   = 32 * w + 8 * sc;
        const float* __restrict__ vrow = vs + rl * PW;
        float* __restrict__ orow = os + rl * OW;

        if (w >= 1 && w <= 14) {
            // interior warps: x in [xb-6, xb+14] all in-bounds
            const float* __restrict__ vw = vrow + xb;
            float s = 0.0f;
            #pragma unroll
            for (int k = 0; k < 13; k++)
                s += vw[k - KHALF];
            #pragma unroll
            for (int i = 0; i < 8; i++) {
                orow[xb + i] = s * k0;  // STS banks (rl+8sc+i)%32: conflict-free
                s += vw[i + KHALF + 1] - vw[i - KHALF];
            }
        } else {
            // boundary warps 0 and 15: reflect
            float s = 0.0f;
            #pragma unroll
            for (int k = 0; k < 13; k++)
                s += vrow[reflect_i(xb - KHALF + k, Wd)];
            #pragma unroll
            for (int i = 0; i < 8; i++) {
                orow[xb + i] = s * k0;
                s += vrow[reflect_i(xb + i + KHALF + 1, Wd)]
                   - vrow[reflect_i(xb + i - KHALF, Wd)];
            }
        }
        __syncwarp();

        // flush own 32-col block: lane = column -> 128B coalesced streaming STG
        const int c = 32 * w + lane;
        #pragma unroll
        for (int row = 0; row < TY; row++) {
            __stcs(&op[(size_t)(y0 + row) * Wd + c], os[row * OW + c]);
        }
    }
}

extern "C" void kernel_launch(void* const* d_in, const int* in_sizes, int n_in,
                              void* d_out, int out_size) {
    const float* input  = (const float*)d_in[0];   // (8,64,512,512) fp32
    const float* kernel = (const float*)d_in[1];   // (1,13,13) fp32 uniform
    float* out = (float*)d_out;

    cudaFuncSetAttribute(boxblur16, cudaFuncAttributeMaxDynamicSharedMemorySize,
                         SMEM_BYTES);

    dim3 grid(Hd / TY, 8 * 64);    // (64 y-tiles, 512 planes) = 32768 CTAs
    boxblur16<<<grid, NT, SMEM_BYTES>>>(input, kernel, out);
}